// round 17
// baseline (speedup 1.0000x reference)
#include <cuda_runtime.h>
#include <math.h>

// Problem dims
#define BB   256
#define TT   1024
#define FF   64
#define EE   256
#define GG   1024      // 4*E
#define KENC 320       // F + E
#define KDEC 256       // E (decoder dense composed into Whh)

// Persistent-kernel tiling: CTA = 32 batch x 16 e-units (64 gate cols), 256 thr
// GEMM: warp w -> (q = w>>2 : K half, rw = w&3 : row octet)
//       lane l -> (rg = l>>3 : rowpair in octet, ep = l&7 : e-pair index)
//       lane computes 2 rows x 8 cols (all 4 gates of e={2ep,2ep+1});
//       acc[row][colpair]: A dup'd (2 dups/k), W native pairs from TWO
//       half-planes (WsA = even e, WsB = odd e) so each LDS.128 is 1 wavefront.
// Combine SYMMETRIC by e-parity: q=0 finalizes even e, q=1 odd e (partner tid^128).
// Barrier is COUNTER-POLL; x staged with prefetch distance 2 (R16 unchanged).
#define NCTA 128
#define STH  256
#define GRPS 8         // independent batch groups (16 CTAs each)
#define ASTR 36        // As[k][b] row stride
#define WSTR2 36       // W half-plane row stride (32 cols + 4 pad)
#define WSTRP 68       // projection W stride

typedef unsigned long long u64;

// ---------------- device scratch (static: no allocation) ----------------
__device__ float g_h[2][EE * BB];                    // hidden state TRANSPOSED [e][b], ping-pong
__device__ float g_Wenc[GG * KENC];                  // [Wih | Whh] rows, K=320
__device__ float g_benc[GG];                         // bih + bhh
__device__ float g_Wdec[GG * KDEC];                  // dWhh + dWih @ Wd
__device__ float g_bdec[GG];                         // dbih + dbhh + dWih @ bd
__device__ float g_WdT[EE * FF];                     // Wd transposed [e][f]
__device__ float g_HallT[(size_t)TT * EE * BB];      // all h_t, TRANSPOSED [t][e][b]
__device__ unsigned g_arrive[GRPS * 32];             // per-group CUMULATIVE arrive counters

__device__ __forceinline__ float sigmoidf_(float v) { return 1.0f / (1.0f + __expf(-v)); }
__device__ __forceinline__ float tanhf_(float v) {
    float t = __expf(2.0f * v);
    return 1.0f - 2.0f / (t + 1.0f);
}

// ---- packed f32x2 helpers ----
__device__ __forceinline__ u64 pack2_dup(float a) {
    u64 r; unsigned u = __float_as_uint(a);
    asm("mov.b64 %0, {%1, %2};" : "=l"(r) : "r"(u), "r"(u));
    return r;
}
__device__ __forceinline__ u64 pack2(float x, float y) {
    u64 r;
    asm("mov.b64 %0, {%1, %2};" : "=l"(r) : "r"(__float_as_uint(x)), "r"(__float_as_uint(y)));
    return r;
}
__device__ __forceinline__ void fma2(u64& d, u64 a, u64 b) {
    asm("fma.rn.f32x2 %0, %1, %2, %3;" : "=l"(d) : "l"(a), "l"(b), "l"(d));
}
__device__ __forceinline__ u64 add2(u64 a, u64 b) {
    u64 r;
    asm("add.rn.f32x2 %0, %1, %2;" : "=l"(r) : "l"(a), "l"(b));
    return r;
}
__device__ __forceinline__ float2 unpack2(u64 v) {
    unsigned lo, hi;
    asm("mov.b64 {%0, %1}, %2;" : "=r"(lo), "=r"(hi) : "l"(v));
    float2 r; r.x = __uint_as_float(lo); r.y = __uint_as_float(hi); return r;
}

// ---------------- init ----------------
__global__ void init_state() {
    int i = blockIdx.x * blockDim.x + threadIdx.x;
    if (i < EE * BB) g_h[0][i] = 0.0f;
    if (i < GRPS) g_arrive[i * 32] = 0;
}

// ---------------- weight packing / decoder composition ----------------
__global__ void pack_weights(const float* __restrict__ eWih, const float* __restrict__ eWhh,
                             const float* __restrict__ ebih, const float* __restrict__ ebhh,
                             const float* __restrict__ dWih, const float* __restrict__ dWhh,
                             const float* __restrict__ dbih, const float* __restrict__ dbhh,
                             const float* __restrict__ Wd,   const float* __restrict__ bd) {
    int row = blockIdx.x;          // 0..1023 (gate row)
    int tid = threadIdx.x;

    for (int k = tid; k < KENC; k += blockDim.x)
        g_Wenc[row * KENC + k] = (k < FF) ? eWih[row * FF + k] : eWhh[row * EE + (k - FF)];

    for (int k = tid; k < KDEC; k += blockDim.x) {
        float s = dWhh[row * EE + k];
        #pragma unroll
        for (int f = 0; f < FF; f++) s += dWih[row * FF + f] * Wd[f * EE + k];
        g_Wdec[row * KDEC + k] = s;
    }
    if (row < EE)
        for (int f = tid; f < FF; f += blockDim.x)
            g_WdT[row * FF + f] = Wd[f * EE + row];
    if (tid == 0) {
        g_benc[row] = ebih[row] + ebhh[row];
        float s = dbih[row] + dbhh[row];
        for (int f = 0; f < FF; f++) s += dWih[row * FF + f] * bd[f];
        g_bdec[row] = s;
    }
}

// ---------------- per-group barrier: cumulative counter poll ----------------
__device__ __forceinline__ void group_sync(unsigned& gen, int grp) {
    __syncthreads();                      // all h stores issued
    gen++;
    if (threadIdx.x == 0) {
        unsigned* arr = &g_arrive[grp * 32];
        unsigned target = gen * 16u;
        unsigned t;
        asm volatile("atom.add.acq_rel.gpu.global.u32 %0, [%1], 1;"
                     : "=r"(t) : "l"(arr) : "memory");
        if (t + 1u != target) {           // not the last arriver -> poll
            unsigned v;
            do {
                asm volatile("ld.acquire.gpu.global.u32 %0, [%1];"
                             : "=r"(v) : "l"(arr) : "memory");
            } while ((int)(v - target) < 0);
        }
    }
    __syncthreads();
}

// ---------------- stage W into two half-planes ----------------
// WsA[k][4*ep + gate] = W[gate][e0 + 2*ep]     (even local e)
// WsB[k][4*ep + gate] = W[gate][e0 + 2*ep + 1] (odd  local e)
template<int K>
__device__ __forceinline__ void stage_W(float* WsA, float* WsB,
                                        const float* __restrict__ gW, int e0) {
    int tid  = threadIdx.x;
    int cp   = tid >> 2;                 // 0..63 logical col
    int q4   = tid & 3;                  // K quarter
    int gate = cp & 3;
    int eloc = cp >> 2;                  // 0..15
    float* dst = (eloc & 1) ? WsB : WsA;
    int col = 4 * (eloc >> 1) + gate;
    const float* src = gW + (size_t)(gate * EE + e0 + eloc) * K + q4 * (K / 4);
    #pragma unroll
    for (int k = 0; k < K / 4; k += 4) {
        float4 v = *(const float4*)(src + k);
        int kk = q4 * (K / 4) + k;
        dst[(kk + 0) * WSTR2 + col] = v.x;
        dst[(kk + 1) * WSTR2 + col] = v.y;
        dst[(kk + 2) * WSTR2 + col] = v.z;
        dst[(kk + 3) * WSTR2 + col] = v.w;
    }
}

// ---------------- one LSTM step ----------------
template<int K, bool ENC>
__device__ __forceinline__ void do_step(
    const float* __restrict__ WsA, const float* __restrict__ WsB,
    float* __restrict__ As, ulonglong2* __restrict__ scr2,
    const float* __restrict__ x, int t, int rp,
    int b0, int e0, const float4 b4, float2& cc,
    float4& xr0, float4& xr1,
    int hall_t, unsigned& gen, int grp)
{
    const float* __restrict__ hr = g_h[rp];
    float*       __restrict__ hw = g_h[rp ^ 1];
    const int tid = threadIdx.x;
    const int w   = tid >> 5;
    const int l   = tid & 31;

    // ---- stage A transposed: h only (x already in place) ----
    const int AOFF = ENC ? FF : 0;
    {
        int bq = (tid & 7) * 4;
        int er = tid >> 3;                   // 0..31
        #pragma unroll
        for (int m = 0; m < 8; m++) {
            int e = er + 32 * m;
            float4 v = __ldcg((const float4*)(hr + e * BB + b0 + bq));
            *(float4*)&As[(AOFF + e) * ASTR + bq] = v;
        }
    }
    __syncthreads();

    // ---- gates GEMM: warp (q = K half, rw = row octet); lane (rg rowpair, ep e-pair) ----
    const int q  = w >> 2, rw = w & 3;
    const int rg = l >> 3, ep = l & 7;
    const int rb = 8 * rw + 2 * rg;         // CTA-local rowpair base
    const int K2 = K / 2;

    u64 acc[2][4];                           // [row in pair][colpair: ifA,goA,ifB,goB]
    #pragma unroll
    for (int r = 0; r < 2; r++)
        #pragma unroll
        for (int c = 0; c < 4; c++) acc[r][c] = 0ull;

    const float* __restrict__ ap  = As  + (q * K2) * ASTR  + rb;
    const float* __restrict__ wpa = WsA + (q * K2) * WSTR2 + 4 * ep;
    const float* __restrict__ wpb = WsB + (q * K2) * WSTR2 + 4 * ep;

    #pragma unroll 8
    for (int k = 0; k < K2; k++) {
        float2 av = *(const float2*)(ap);        // rows rb, rb+1 (8-way bcast, 1 wf)
        float4 wa = *(const float4*)(wpa);       // (i,f,g,o) of e=2ep   (1 wf)
        float4 wb = *(const float4*)(wpb);       // (i,f,g,o) of e=2ep+1 (1 wf)
        u64 WA01 = ((const u64*)&wa)[0], WA23 = ((const u64*)&wa)[1];
        u64 WB01 = ((const u64*)&wb)[0], WB23 = ((const u64*)&wb)[1];
        u64 A0 = pack2_dup(av.x), A1 = pack2_dup(av.y);   // only 2 dups/k
        fma2(acc[0][0], A0, WA01);  fma2(acc[0][1], A0, WA23);
        fma2(acc[0][2], A0, WB01);  fma2(acc[0][3], A0, WB23);
        fma2(acc[1][0], A1, WA01);  fma2(acc[1][1], A1, WA23);
        fma2(acc[1][2], A1, WB01);  fma2(acc[1][3], A1, WB23);
        ap += ASTR;  wpa += WSTR2;  wpb += WSTR2;
    }

    // ---- symmetric combine by e-parity: dump FOREIGN e's colpairs ----
    // q=0 finalizes e_even (cp 0,1), dumps cp 2,3; q=1 finalizes e_odd, dumps cp 0,1.
    {
        const int fc = q ? 0 : 2;
        scr2[tid]       = make_ulonglong2(acc[0][fc], acc[0][fc + 1]);   // row rb
        scr2[256 + tid] = make_ulonglong2(acc[1][fc], acc[1][fc + 1]);   // row rb+1
    }
    __syncthreads();

    // ---- all 8 warps: add partner partials + finalize 2 rows x 1 e ----
    {
        const int oc = q ? 2 : 0;
        const int pt = tid ^ 128;            // partner (other K half, same rows/ep)
        ulonglong2 p0 = scr2[pt];
        ulonglong2 p1 = scr2[256 + pt];
        u64 sIF0 = add2(acc[0][oc],     p0.x);   // row rb:   (i,f)
        u64 sGO0 = add2(acc[0][oc + 1], p0.y);   // row rb:   (g,o)
        u64 sIF1 = add2(acc[1][oc],     p1.x);   // row rb+1: (i,f)
        u64 sGO1 = add2(acc[1][oc + 1], p1.y);   // row rb+1: (g,o)

        const int e = e0 + 2 * ep + q;       // q selects even/odd e
        const int b = b0 + rb;               // rows rb, rb+1
        float2 if0 = unpack2(sIF0), go0 = unpack2(sGO0);
        float2 if1 = unpack2(sIF1), go1 = unpack2(sGO1);
        float i0 = sigmoidf_(if0.x + b4.x), f0v = sigmoidf_(if0.y + b4.y);
        float g0 = tanhf_  (go0.x + b4.z), o0v = sigmoidf_(go0.y + b4.w);
        float i1 = sigmoidf_(if1.x + b4.x), f1v = sigmoidf_(if1.y + b4.y);
        float g1 = tanhf_  (go1.x + b4.z), o1v = sigmoidf_(go1.y + b4.w);
        float c0 = f0v * cc.x + i0 * g0;  cc.x = c0;
        float c1 = f1v * cc.y + i1 * g1;  cc.y = c1;
        float h0 = o0v * tanhf_(c0);
        float h1 = o1v * tanhf_(c1);
        u64 hp = pack2(h0, h1);
        *(u64*)(hw + e * BB + b) = hp;
        if (hall_t >= 0)
            *(u64*)(g_HallT + ((size_t)hall_t * EE + e) * BB + b) = hp;
    }

    // ---- ENC: STS x_{t+1}, prefetch x_{t+2} (barrier-wait shadow) ----
    if (ENC) {
        if (t + 1 < TT) {
            int f = w * 8;
            As[(f + 0) * ASTR + l] = xr0.x;  As[(f + 1) * ASTR + l] = xr0.y;
            As[(f + 2) * ASTR + l] = xr0.z;  As[(f + 3) * ASTR + l] = xr0.w;
            As[(f + 4) * ASTR + l] = xr1.x;  As[(f + 5) * ASTR + l] = xr1.y;
            As[(f + 6) * ASTR + l] = xr1.z;  As[(f + 7) * ASTR + l] = xr1.w;
        }
        if (t + 2 < TT) {
            const float* xs = x + (size_t)(b0 + l) * (TT * FF) + (size_t)(t + 2) * FF + w * 8;
            xr0 = *(const float4*)(xs);
            xr1 = *(const float4*)(xs + 4);
        }
    }

    group_sync(gen, grp);
}

// ---------------- the persistent recurrence kernel ----------------
__global__ void __launch_bounds__(STH, 1)
persistent_kernel(const float* __restrict__ x)
{
    extern __shared__ float smem[];
    float* WsA = smem;                                   // [K][WSTR2]  46,080B
    float* WsB = smem + KENC * WSTR2;                    // [K][WSTR2]  46,080B
    float* As  = smem + 2 * KENC * WSTR2;                // [K][ASTR]   46,080B
    ulonglong2* scr2 = (ulonglong2*)(smem + KENC * (2 * WSTR2 + ASTR));  // 8KB

    const int tid = threadIdx.x;
    const int cta = blockIdx.x;              // 0..127
    const int grp = cta & 7;                 // batch group (independent)
    const int b0  = grp * 32;
    const int e0  = (cta >> 3) * 16;
    const int eg  = e0 + 2 * (tid & 7) + (tid >> 7);   // this thread's finalize e
    const int w   = tid >> 5;
    const int l   = tid & 31;

    unsigned gen = 0;
    float2 cc = make_float2(0.f, 0.f);
    float4 xr0 = make_float4(0.f, 0.f, 0.f, 0.f);
    float4 xr1 = xr0;

    // ===== encoder phase =====
    float4 b4 = make_float4(g_benc[eg], g_benc[EE + eg], g_benc[2 * EE + eg], g_benc[3 * EE + eg]);
    stage_W<KENC>(WsA, WsB, g_Wenc, e0);
    {   // stage x_0 into As, prefetch x_1 into regs
        const float* xs = x + (size_t)(b0 + l) * (TT * FF) + w * 8;
        float4 v0 = *(const float4*)(xs);
        float4 v1 = *(const float4*)(xs + 4);
        int f = w * 8;
        As[(f + 0) * ASTR + l] = v0.x;  As[(f + 1) * ASTR + l] = v0.y;
        As[(f + 2) * ASTR + l] = v0.z;  As[(f + 3) * ASTR + l] = v0.w;
        As[(f + 4) * ASTR + l] = v1.x;  As[(f + 5) * ASTR + l] = v1.y;
        As[(f + 6) * ASTR + l] = v1.z;  As[(f + 7) * ASTR + l] = v1.w;
        const float* xs1 = xs + FF;
        xr0 = *(const float4*)(xs1);
        xr1 = *(const float4*)(xs1 + 4);
    }
    __syncthreads();
    for (int t = 0; t < TT; t++)
        do_step<KENC, true>(WsA, WsB, As, scr2, x, t, t & 1, b0, e0, b4, cc, xr0, xr1,
                            (t == TT - 1) ? 0 : -1, gen, grp);

    // ===== decoder phase (dense projection composed into Whh) =====
    b4 = make_float4(g_bdec[eg], g_bdec[EE + eg], g_bdec[2 * EE + eg], g_bdec[3 * EE + eg]);
    __syncthreads();
    stage_W<KDEC>(WsA, WsB, g_Wdec, e0);
    __syncthreads();
    for (int t = 1; t < TT; t++)
        do_step<KDEC, false>(WsA, WsB, As, scr2, nullptr, 0, (t - 1) & 1, b0, e0, b4, cc, xr0, xr1,
                             t, gen, grp);
}

// ---------------- final projection: out[t*B+b][f] = HallT[t][:,b] . WdT[:,f] + bd ----
__global__ void __launch_bounds__(128)
project2(const float* __restrict__ bd, float* __restrict__ out)
{
    extern __shared__ float smem[];
    float* Ws = smem;                        // [256][WSTRP]
    float* As = smem + KDEC * WSTRP;         // [256][ASTR]

    const int tid = threadIdx.x;
    const int wid = tid >> 5;
    const int lid = tid & 31;
    const int t   = blockIdx.x >> 3;
    const int b0  = (blockIdx.x & 7) * 32;

    #pragma unroll
    for (int j = 0; j < 32; j++) {
        int idx = tid + 128 * j;             // 0..4095
        int e = idx >> 4, fq = (idx & 15) * 4;
        float4 v = *(const float4*)(g_WdT + e * FF + fq);
        *(float4*)&Ws[e * WSTRP + fq] = v;
    }
    {
        int bq = (tid & 7) * 4;
        int er = tid >> 3;
        #pragma unroll
        for (int m = 0; m < 16; m++) {
            int e = er + 16 * m;
            float4 v = *(const float4*)(g_HallT + ((size_t)t * EE + e) * BB + b0 + bq);
            *(float4*)&As[e * ASTR + bq] = v;
        }
    }
    __syncthreads();

    u64 acc[4][2];
    #pragma unroll
    for (int j = 0; j < 4; j++) { acc[j][0] = 0ull; acc[j][1] = 0ull; }

    const float* __restrict__ arow = As + 8 * wid;
    const float* __restrict__ wrow = Ws + 2 * lid;

    #pragma unroll 4
    for (int k = 0; k < KDEC; k++) {
        float4 a01 = *(const float4*)(arow + k * ASTR);
        float4 a23 = *(const float4*)(arow + k * ASTR + 4);
        float2 wv  = *(const float2*)(wrow + k * WSTRP);
        u64 wd0 = pack2_dup(wv.x);
        u64 wd1 = pack2_dup(wv.y);
        u64 A0 = ((const u64*)&a01)[0], A1 = ((const u64*)&a01)[1];
        u64 A2 = ((const u64*)&a23)[0], A3 = ((const u64*)&a23)[1];
        fma2(acc[0][0], A0, wd0);  fma2(acc[0][1], A0, wd1);
        fma2(acc[1][0], A1, wd0);  fma2(acc[1][1], A1, wd1);
        fma2(acc[2][0], A2, wd0);  fma2(acc[2][1], A2, wd1);
        fma2(acc[3][0], A3, wd0);  fma2(acc[3][1], A3, wd1);
    }

    const float bf0 = bd[2 * lid];
    const float bf1 = bd[2 * lid + 1];
    #pragma unroll
    for (int j = 0; j < 4; j++) {
        int r0 = b0 + 8 * wid + 2 * j;
        float2 v0 = unpack2(acc[j][0]);
        float2 v1 = unpack2(acc[j][1]);
        size_t row0 = (size_t)t * BB + r0;
        *(u64*)(out + row0 * FF + 2 * lid)        = pack2(v0.x + bf0, v1.x + bf1);
        *(u64*)(out + (row0 + 1) * FF + 2 * lid)  = pack2(v0.y + bf0, v1.y + bf1);
    }
}

// ---------------- launch ----------------
extern "C" void kernel_launch(void* const* d_in, const int* in_sizes, int n_in,
                              void* d_out, int out_size) {
    const float* x    = (const float*)d_in[0];
    const float* eWih = (const float*)d_in[1];
    const float* eWhh = (const float*)d_in[2];
    const float* ebih = (const float*)d_in[3];
    const float* ebhh = (const float*)d_in[4];
    const float* dWih = (const float*)d_in[5];
    const float* dWhh = (const float*)d_in[6];
    const float* dbih = (const float*)d_in[7];
    const float* dbhh = (const float*)d_in[8];
    const float* Wd   = (const float*)d_in[9];
    const float* bd   = (const float*)d_in[10];
    float* out = (float*)d_out;

    const int smem_main = KENC * (2 * WSTR2 + ASTR) * (int)sizeof(float) + 512 * (int)sizeof(ulonglong2);
    const int smem_proj = KDEC * (WSTRP + ASTR) * (int)sizeof(float);
    cudaFuncSetAttribute(persistent_kernel, cudaFuncAttributeMaxDynamicSharedMemorySize, smem_main);
    cudaFuncSetAttribute(project2,          cudaFuncAttributeMaxDynamicSharedMemorySize, smem_proj);

    init_state<<<(EE * BB + 255) / 256, 256>>>();
    pack_weights<<<GG, 256>>>(eWih, eWhh, ebih, ebhh, dWih, dWhh, dbih, dbhh, Wd, bd);
    persistent_kernel<<<NCTA, STH, smem_main>>>(x);
    project2<<<(TT * BB) / 32, 128, smem_proj>>>(bd, out);
}